// round 6
// baseline (speedup 1.0000x reference)
#include <cuda_runtime.h>
#include <cuda_bf16.h>
#include <mma.h>

using namespace nvcuda;

// Problem-fixed shapes
#define MAXN 50000
#define MAXE 600000
#define D 128
#define ED 16

// ---------------- device scratch (static: no allocs allowed) ----------------
__device__ float g_agg[MAXN * D];
__device__ float g_deg[MAXN];
__device__ float g_hnew[MAXN * D];
__device__ float g_neigh[MAXN * D];
__device__ float g_t1[MAXN * D];
__device__ float g_t2[MAXN * D];
__device__ float g_stats[3 * 256];
__device__ float g_mom[16 + 256];
__device__ float g_scale[3 * 128];
__device__ float g_shift[3 * 128];
__device__ int   g_is64;

// ---------------- index dtype detection ----------------
__global__ void detect_idx(const unsigned long long* __restrict__ ei, int E)
{
    if (threadIdx.x == 0 && blockIdx.x == 0) {
        int n = E < 1024 ? E : 1024;
        int is64 = 1;
        for (int i = 0; i < n; i++)
            if (ei[i] >> 32) { is64 = 0; break; }
        g_is64 = is64;
    }
}

__device__ __forceinline__ int load_idx(const void* ei, long long pos, int is64)
{
    if (is64) return (int)((const long long*)ei)[pos];
    return ((const int*)ei)[pos];
}

// ---------------- edge moments: S = sum attr, M = sum attr attr^T ------------
__global__ void __launch_bounds__(256) edge_moments(
    const float* __restrict__ attr, int E, float* __restrict__ mom)
{
    __shared__ float sa[128 * ED];
    int tid = threadIdx.x;
    int k = tid & 15, l = tid >> 4;
    float m = 0.f, s = 0.f;
    for (int base = blockIdx.x * 128; base < E; base += gridDim.x * 128) {
        int ne = min(128, E - base);
        __syncthreads();
        for (int i = tid; i < ne * ED; i += 256)
            sa[i] = attr[(long long)base * ED + i];
        __syncthreads();
        for (int e = 0; e < ne; e++) {
            float ak = sa[e * ED + k];
            float al = sa[e * ED + l];
            m = fmaf(ak, al, m);
            if (l == 0) s += ak;
        }
    }
    atomicAdd(&mom[16 + l * 16 + k], m);
    if (l == 0) atomicAdd(&mom[k], s);
}

// ---------------- finalize edge BN from moments ------------------------------
__global__ void __launch_bounds__(128) finalize_ee_bn(
    const float* __restrict__ mom, const float* __restrict__ w1,
    const float* __restrict__ b1, const float* __restrict__ gamma,
    const float* __restrict__ beta, float invE,
    float* __restrict__ scale, float* __restrict__ shift)
{
    __shared__ float S[16], M[256];
    int c = threadIdx.x;
    if (c < 16) S[c] = mom[c];
    M[c] = mom[16 + c];
    M[128 + c] = mom[144 + c];
    __syncthreads();

    float wc[16];
#pragma unroll
    for (int k = 0; k < 16; k++) wc[k] = w1[k * D + c];
    float sw = 0.f;
#pragma unroll
    for (int k = 0; k < 16; k++) sw = fmaf(S[k], wc[k], sw);
    float bc = b1[c];
    float mean = sw * invE + bc;
    float q = 0.f;
#pragma unroll
    for (int k = 0; k < 16; k++) {
        float t = 0.f;
#pragma unroll
        for (int l = 0; l < 16; l++) t = fmaf(M[k * 16 + l], wc[l], t);
        q = fmaf(wc[k], t, q);
    }
    float ex2 = q * invE + 2.f * bc * sw * invE + bc * bc;
    float var = ex2 - mean * mean;
    float inv = rsqrtf(var + 1e-5f);
    float sc = gamma[c] * inv;
    scale[c] = sc;
    shift[c] = beta[c] - mean * sc;
}

// ---------------- finalize BN: scale/shift from colstats ---------------------
__global__ void finalize_bn(const float* __restrict__ stats,
                            const float* __restrict__ gamma,
                            const float* __restrict__ beta,
                            float invn, float* __restrict__ scale,
                            float* __restrict__ shift)
{
    int c = threadIdx.x;
    float mean = stats[c] * invn;
    float var = stats[128 + c] * invn - mean * mean;
    float inv = rsqrtf(var + 1e-5f);
    float sc = gamma[c] * inv;
    scale[c] = sc;
    shift[c] = beta[c] - mean * sc;
}

// ---------------- edge pass 2: scatter relu(BN(t)) rows to agg[dst] ---------
__global__ void __launch_bounds__(256) edge_pass2(
    const float* __restrict__ attr, const void* __restrict__ ei,
    const float* __restrict__ w1, const float* __restrict__ b1,
    const float* __restrict__ scale, const float* __restrict__ shift,
    int E, int N, float* __restrict__ agg, float* __restrict__ deg)
{
    __shared__ float sa[64 * ED];
    __shared__ int sd[64];
    int lane = threadIdx.x & 31;
    int grp = threadIdx.x >> 5;
    int c4 = lane * 4;
    int is64 = g_is64;

    float4 w[ED];
#pragma unroll
    for (int k = 0; k < ED; k++) w[k] = *(const float4*)&w1[k * D + c4];
    float4 bb = *(const float4*)&b1[c4];
    float4 sc = *(const float4*)&scale[c4];
    float4 sh = *(const float4*)&shift[c4];
    sh.x = fmaf(bb.x, sc.x, sh.x);
    sh.y = fmaf(bb.y, sc.y, sh.y);
    sh.z = fmaf(bb.z, sc.z, sh.z);
    sh.w = fmaf(bb.w, sc.w, sh.w);

    for (int base = blockIdx.x * 64; base < E; base += gridDim.x * 64) {
        int ne = min(64, E - base);
        __syncthreads();
        for (int i = threadIdx.x; i < ne * ED; i += 256)
            sa[i] = attr[(long long)base * ED + i];
        for (int i = threadIdx.x; i < ne; i += 256)
            sd[i] = load_idx(ei, (long long)E + base + i, is64);
        __syncthreads();
        for (int e = grp; e < ne; e += 8) {
            int d = sd[e];
            if ((unsigned)d >= (unsigned)N) continue;
            float4 acc = make_float4(0.f, 0.f, 0.f, 0.f);
#pragma unroll
            for (int k = 0; k < ED; k++) {
                float a = sa[e * ED + k];
                acc.x = fmaf(a, w[k].x, acc.x);
                acc.y = fmaf(a, w[k].y, acc.y);
                acc.z = fmaf(a, w[k].z, acc.z);
                acc.w = fmaf(a, w[k].w, acc.w);
            }
            float4 y;
            y.x = fmaxf(fmaf(acc.x, sc.x, sh.x), 0.f);
            y.y = fmaxf(fmaf(acc.y, sc.y, sh.y), 0.f);
            y.z = fmaxf(fmaf(acc.z, sc.z, sh.z), 0.f);
            y.w = fmaxf(fmaf(acc.w, sc.w, sh.w), 0.f);
            atomicAdd((float4*)&agg[(long long)d * D + c4], y);
            if (lane == 0) atomicAdd(&deg[d], 1.0f);
        }
    }
}

// ---------------- neighbor scatter: neigh[dst] += h_new[src] ----------------
__global__ void __launch_bounds__(256) neigh_scatter(
    const void* __restrict__ ei, const float* __restrict__ hnew,
    float* __restrict__ neigh, int E, int N)
{
    int lane = threadIdx.x & 31;
    int grp = threadIdx.x >> 5;
    int c4 = lane * 4;
    int is64 = g_is64;
    for (int e = blockIdx.x * 8 + grp; e < E; e += gridDim.x * 8) {
        int s = load_idx(ei, e, is64);
        int d = load_idx(ei, (long long)E + e, is64);
        if ((unsigned)s >= (unsigned)N || (unsigned)d >= (unsigned)N) continue;
        float4 v = *(const float4*)&hnew[(long long)s * D + c4];
        atomicAdd((float4*)&neigh[(long long)d * D + c4], v);
    }
}

// ---------------- 3xTF32 tensor-core GEMM, 128-wide K, fused pre/post -------
// MODE 0: out = A@W + hin + deg*bias          (A = agg, W = ee_w2)
// MODE 1: out = (A + A2)@W + bias             (A = hnew, A2 = neigh, W = mlp_w1)
// MODE 2: out = relu(A*scale+shift)@W + bias  (A = t1, W = mlp_w2)
#define KC  64
#define LDA 72
#define LDB 136
#define LDC 136
// smem floats: Ahi[128*72] Alo[128*72] Bhi[64*136] Blo[64*136]
#define GEMM_SMEM ((128 * LDA * 2 + KC * LDB * 2) * 4)

template <int MODE>
__global__ void __launch_bounds__(256) gemm128(
    const float* __restrict__ A, const float* __restrict__ A2,
    const float* __restrict__ W, const float* __restrict__ bias,
    const float* __restrict__ scale, const float* __restrict__ shift,
    const float* __restrict__ hin, const float* __restrict__ degv,
    float* __restrict__ out, int N)
{
    extern __shared__ float sm[];
    float* Ahi = sm;
    float* Alo = sm + 128 * LDA;
    float* Bhi = sm + 128 * LDA * 2;
    float* Blo = Bhi + KC * LDB;
    float* Cs  = sm;  // reused for epilogue staging

    int tid = threadIdx.x;
    int row0 = blockIdx.x * 128;
    int warp = tid >> 5;
    int wrow = warp >> 2;   // 0..1 -> 64-row band
    int wcol = warp & 3;    // 0..3 -> 32-col band

    wmma::fragment<wmma::accumulator, 16, 16, 8, float> acc[4][2];
#pragma unroll
    for (int i = 0; i < 4; i++)
#pragma unroll
        for (int j = 0; j < 2; j++) wmma::fill_fragment(acc[i][j], 0.f);

    for (int kc = 0; kc < D; kc += KC) {
        __syncthreads();
        // load A chunk [128 x 64] with fused pre-op, split hi/lo
        for (int i = tid; i < 128 * (KC / 4); i += 256) {
            int r = i >> 4;            // KC/4 = 16 float4 per row
            int c = (i & 15) * 4;
            int row = row0 + r;
            float4 v = make_float4(0.f, 0.f, 0.f, 0.f);
            if (row < N) {
                v = *(const float4*)&A[(long long)row * D + kc + c];
                if (MODE == 1) {
                    float4 v2 = *(const float4*)&A2[(long long)row * D + kc + c];
                    v.x += v2.x; v.y += v2.y; v.z += v2.z; v.w += v2.w;
                }
                if (MODE == 2) {
                    float4 scv = *(const float4*)&scale[kc + c];
                    float4 shv = *(const float4*)&shift[kc + c];
                    v.x = fmaxf(fmaf(v.x, scv.x, shv.x), 0.f);
                    v.y = fmaxf(fmaf(v.y, scv.y, shv.y), 0.f);
                    v.z = fmaxf(fmaf(v.z, scv.z, shv.z), 0.f);
                    v.w = fmaxf(fmaf(v.w, scv.w, shv.w), 0.f);
                }
            }
            float hx = wmma::__float_to_tf32(v.x);
            float hy = wmma::__float_to_tf32(v.y);
            float hz = wmma::__float_to_tf32(v.z);
            float hw = wmma::__float_to_tf32(v.w);
            float* ph = &Ahi[r * LDA + c];
            float* pl = &Alo[r * LDA + c];
            ph[0] = hx; ph[1] = hy; ph[2] = hz; ph[3] = hw;
            pl[0] = v.x - hx; pl[1] = v.y - hy; pl[2] = v.z - hz; pl[3] = v.w - hw;
        }
        // load B chunk [64 x 128] (W rows kc..kc+63), split hi/lo
        for (int i = tid; i < KC * 32; i += 256) {
            int r = i >> 5;
            int c = (i & 31) * 4;
            float4 v = *(const float4*)&W[(long long)(kc + r) * D + c];
            float hx = wmma::__float_to_tf32(v.x);
            float hy = wmma::__float_to_tf32(v.y);
            float hz = wmma::__float_to_tf32(v.z);
            float hw = wmma::__float_to_tf32(v.w);
            float* ph = &Bhi[r * LDB + c];
            float* pl = &Blo[r * LDB + c];
            ph[0] = hx; ph[1] = hy; ph[2] = hz; ph[3] = hw;
            pl[0] = v.x - hx; pl[1] = v.y - hy; pl[2] = v.z - hz; pl[3] = v.w - hw;
        }
        __syncthreads();

#pragma unroll
        for (int ks = 0; ks < KC; ks += 8) {
            wmma::fragment<wmma::matrix_b, 16, 16, 8, wmma::precision::tf32, wmma::row_major> bh[2], bl[2];
#pragma unroll
            for (int j = 0; j < 2; j++) {
                wmma::load_matrix_sync(bh[j], Bhi + ks * LDB + wcol * 32 + j * 16, LDB);
                wmma::load_matrix_sync(bl[j], Blo + ks * LDB + wcol * 32 + j * 16, LDB);
            }
#pragma unroll
            for (int i = 0; i < 4; i++) {
                wmma::fragment<wmma::matrix_a, 16, 16, 8, wmma::precision::tf32, wmma::row_major> ah, al;
                wmma::load_matrix_sync(ah, Ahi + (wrow * 64 + i * 16) * LDA + ks, LDA);
                wmma::load_matrix_sync(al, Alo + (wrow * 64 + i * 16) * LDA + ks, LDA);
#pragma unroll
                for (int j = 0; j < 2; j++) {
                    wmma::mma_sync(acc[i][j], ah, bh[j], acc[i][j]);
                    wmma::mma_sync(acc[i][j], ah, bl[j], acc[i][j]);
                    wmma::mma_sync(acc[i][j], al, bh[j], acc[i][j]);
                }
            }
        }
    }
    __syncthreads();
    // stage C through smem
#pragma unroll
    for (int i = 0; i < 4; i++)
#pragma unroll
        for (int j = 0; j < 2; j++)
            wmma::store_matrix_sync(Cs + (wrow * 64 + i * 16) * LDC + wcol * 32 + j * 16,
                                    acc[i][j], LDC, wmma::mem_row_major);
    __syncthreads();

    // fused epilogue
    for (int idx = tid; idx < 128 * 32; idx += 256) {
        int r = idx >> 5;
        int c4 = (idx & 31) * 4;
        int row = row0 + r;
        if (row >= N) continue;
        float4 cv = *(float4*)&Cs[r * LDC + c4];
        float4 bs = *(const float4*)&bias[c4];
        float4 o;
        if (MODE == 0) {
            float dg = degv[row];
            float4 hv = *(const float4*)&hin[(long long)row * D + c4];
            o.x = cv.x + hv.x + dg * bs.x;
            o.y = cv.y + hv.y + dg * bs.y;
            o.z = cv.z + hv.z + dg * bs.z;
            o.w = cv.w + hv.w + dg * bs.w;
        } else {
            o.x = cv.x + bs.x;
            o.y = cv.y + bs.y;
            o.z = cv.z + bs.z;
            o.w = cv.w + bs.w;
        }
        *(float4*)&out[(long long)row * D + c4] = o;
    }
}

// ---------------- column stats over [N,128] ----------------
__global__ void __launch_bounds__(256) colstats(
    const float* __restrict__ X, int N, float* __restrict__ stats)
{
    int c = threadIdx.x & 127;
    int half = threadIdx.x >> 7;
    float s1 = 0.f, s2 = 0.f;
    for (int r = blockIdx.x * 2 + half; r < N; r += gridDim.x * 2) {
        float v = X[(long long)r * D + c];
        s1 += v;
        s2 += v * v;
    }
    atomicAdd(&stats[c], s1);
    atomicAdd(&stats[128 + c], s2);
}

// ---------------- zero scratch buffers ----------------
__global__ void __launch_bounds__(256) zero_scratch(
    float* __restrict__ agg, float* __restrict__ neigh,
    float* __restrict__ deg, float* __restrict__ stats,
    float* __restrict__ mom, int N)
{
    int gtid = blockIdx.x * blockDim.x + threadIdx.x;
    int total = N * D;
    for (int i = gtid; i < total; i += gridDim.x * blockDim.x) {
        agg[i] = 0.f;
        neigh[i] = 0.f;
    }
    for (int i = gtid; i < N; i += gridDim.x * blockDim.x)
        deg[i] = 0.f;
    if (gtid < 768) stats[gtid] = 0.f;
    if (gtid < 272) mom[gtid] = 0.f;
}

// ---------------- final eltwise: out = relu(bn(t2)) ----------------
__global__ void __launch_bounds__(256) bn_relu_out(
    const float* __restrict__ t2, const float* __restrict__ scale,
    const float* __restrict__ shift, float* __restrict__ out, int N)
{
    int total4 = N * 32;
    for (int idx = blockIdx.x * blockDim.x + threadIdx.x; idx < total4;
         idx += gridDim.x * blockDim.x) {
        int c4 = (idx & 31) * 4;
        float4 v = *(const float4*)&t2[(long long)idx * 4];
        float4 sc = *(const float4*)&scale[c4];
        float4 sh = *(const float4*)&shift[c4];
        float4 o;
        o.x = fmaxf(fmaf(v.x, sc.x, sh.x), 0.f);
        o.y = fmaxf(fmaf(v.y, sc.y, sh.y), 0.f);
        o.z = fmaxf(fmaf(v.z, sc.z, sh.z), 0.f);
        o.w = fmaxf(fmaf(v.w, sc.w, sh.w), 0.f);
        *(float4*)&out[(long long)idx * 4] = o;
    }
}

// ---------------- launch ----------------
extern "C" void kernel_launch(void* const* d_in, const int* in_sizes, int n_in,
                              void* d_out, int out_size)
{
    const float* h        = (const float*)d_in[0];
    const void*  ei       = d_in[1];
    const float* attr     = (const float*)d_in[2];
    const float* ee_w1    = (const float*)d_in[3];
    const float* ee_b1    = (const float*)d_in[4];
    const float* ee_g1    = (const float*)d_in[5];
    const float* ee_bb1   = (const float*)d_in[6];
    const float* ee_w2    = (const float*)d_in[7];
    const float* ee_b2    = (const float*)d_in[8];
    const float* mlp_w1   = (const float*)d_in[9];
    const float* mlp_b1   = (const float*)d_in[10];
    const float* mlp_g1   = (const float*)d_in[11];
    const float* mlp_bb1  = (const float*)d_in[12];
    const float* mlp_w2   = (const float*)d_in[13];
    const float* mlp_b2   = (const float*)d_in[14];
    const float* mlp_g2   = (const float*)d_in[15];
    const float* mlp_bb2  = (const float*)d_in[16];

    int N = in_sizes[0] / D;
    int E = in_sizes[1] / 2;
    float* out = (float*)d_out;

    float *p_agg, *p_deg, *p_hnew, *p_neigh, *p_t1, *p_t2, *p_stats, *p_mom, *p_scale, *p_shift;
    cudaGetSymbolAddress((void**)&p_agg, g_agg);
    cudaGetSymbolAddress((void**)&p_deg, g_deg);
    cudaGetSymbolAddress((void**)&p_hnew, g_hnew);
    cudaGetSymbolAddress((void**)&p_neigh, g_neigh);
    cudaGetSymbolAddress((void**)&p_t1, g_t1);
    cudaGetSymbolAddress((void**)&p_t2, g_t2);
    cudaGetSymbolAddress((void**)&p_stats, g_stats);
    cudaGetSymbolAddress((void**)&p_mom, g_mom);
    cudaGetSymbolAddress((void**)&p_scale, g_scale);
    cudaGetSymbolAddress((void**)&p_shift, g_shift);

    cudaFuncSetAttribute(gemm128<0>, cudaFuncAttributeMaxDynamicSharedMemorySize, GEMM_SMEM);
    cudaFuncSetAttribute(gemm128<1>, cudaFuncAttributeMaxDynamicSharedMemorySize, GEMM_SMEM);
    cudaFuncSetAttribute(gemm128<2>, cudaFuncAttributeMaxDynamicSharedMemorySize, GEMM_SMEM);

    int tiles = (N + 127) / 128;

    detect_idx<<<1, 32>>>((const unsigned long long*)ei, E);
    zero_scratch<<<592, 256>>>(p_agg, p_neigh, p_deg, p_stats, p_mom, N);

    // edge encoder BN stats via closed-form moments
    edge_moments<<<1184, 256>>>(attr, E, p_mom);
    finalize_ee_bn<<<1, 128>>>(p_mom, ee_w1, ee_b1, ee_g1, ee_bb1,
                               1.0f / (float)E, p_scale, p_shift);

    // edge encoder: apply + scatter relu rows (2nd Linear deferred to node GEMM)
    edge_pass2<<<1184, 256>>>(attr, ei, ee_w1, ee_b1, p_scale, p_shift, E, N, p_agg, p_deg);

    // h_new = h + agg@ee_w2 + deg*ee_b2
    gemm128<0><<<tiles, 256, GEMM_SMEM>>>(p_agg, nullptr, ee_w2, ee_b2,
                                          nullptr, nullptr, h, p_deg, p_hnew, N);

    // neigh = segment_sum(h_new[src], dst)
    neigh_scatter<<<1184, 256>>>(ei, p_hnew, p_neigh, E, N);

    // t1 = (h_new + neigh) @ mlp_w1 + b1
    gemm128<1><<<tiles, 256, GEMM_SMEM>>>(p_hnew, p_neigh, mlp_w1, mlp_b1,
                                          nullptr, nullptr, nullptr, nullptr, p_t1, N);
    colstats<<<592, 256>>>(p_t1, N, p_stats + 256);
    finalize_bn<<<1, 128>>>(p_stats + 256, mlp_g1, mlp_bb1, 1.0f / (float)N,
                            p_scale + 128, p_shift + 128);

    // t2 = relu(bn(t1)) @ mlp_w2 + b2
    gemm128<2><<<tiles, 256, GEMM_SMEM>>>(p_t1, nullptr, mlp_w2, mlp_b2,
                                          p_scale + 128, p_shift + 128,
                                          nullptr, nullptr, p_t2, N);
    colstats<<<592, 256>>>(p_t2, N, p_stats + 512);
    finalize_bn<<<1, 128>>>(p_stats + 512, mlp_g2, mlp_bb2, 1.0f / (float)N,
                            p_scale + 256, p_shift + 256);

    // out = relu(bn(t2))
    int g = min((N * 32 + 255) / 256, 4096);
    bn_relu_out<<<g, 256>>>(p_t2, p_scale + 256, p_shift + 256, out, N);
}

// round 7
// speedup vs baseline: 1.1646x; 1.1646x over previous
#include <cuda_runtime.h>
#include <cuda_bf16.h>

// Problem-fixed shapes
#define MAXN 50000
#define MAXE 600000
#define D 128
#define ED 16

// ---------------- device scratch (static: no allocs allowed) ----------------
__device__ float g_agg[MAXN * D];
__device__ float g_deg[MAXN];
__device__ float g_hnew[MAXN * D];
__device__ float g_neigh[MAXN * D];
__device__ float g_t1[MAXN * D];
__device__ float g_t2[MAXN * D];
__device__ float g_stats[3 * 256];
__device__ float g_mom[16 + 256];
__device__ float g_scale[3 * 128];
__device__ float g_shift[3 * 128];
__device__ int   g_is64;
// CSR by destination
__device__ int   g_count[MAXN];
__device__ int   g_rowptr[MAXN];
__device__ int   g_next[MAXN];
__device__ int   g_eid[MAXE];     // edge id per CSR slot (for attr)
__device__ int   g_srcid[MAXE];   // src node per CSR slot (for hnew gather)
__device__ int   g_partial[64];

// ---------------- index dtype detection ----------------
__global__ void detect_idx(const unsigned long long* __restrict__ ei, int E)
{
    if (threadIdx.x == 0 && blockIdx.x == 0) {
        int n = E < 1024 ? E : 1024;
        int is64 = 1;
        for (int i = 0; i < n; i++)
            if (ei[i] >> 32) { is64 = 0; break; }
        g_is64 = is64;
    }
}

__device__ __forceinline__ int load_idx(const void* ei, long long pos, int is64)
{
    if (is64) return (int)((const long long*)ei)[pos];
    return ((const int*)ei)[pos];
}

// ---------------- zero small accumulators + count ----------------
__global__ void __launch_bounds__(256) zero_small(
    int* __restrict__ count, float* __restrict__ stats,
    float* __restrict__ mom, int N)
{
    int gtid = blockIdx.x * blockDim.x + threadIdx.x;
    for (int i = gtid; i < N; i += gridDim.x * blockDim.x) count[i] = 0;
    if (gtid < 768) stats[gtid] = 0.f;
    if (gtid < 272) mom[gtid] = 0.f;
}

// ---------------- histogram of dst ----------------
__global__ void __launch_bounds__(256) hist_dst(
    const void* __restrict__ ei, int E, int N, int* __restrict__ count)
{
    int is64 = g_is64;
    for (int e = blockIdx.x * blockDim.x + threadIdx.x; e < E;
         e += gridDim.x * blockDim.x) {
        int d = load_idx(ei, (long long)E + e, is64);
        if ((unsigned)d < (unsigned)N) atomicAdd(&count[d], 1);
    }
}

// ---------------- 3-kernel exclusive scan over count[N] ----------------
#define SCAN_C 1024
__global__ void __launch_bounds__(256) scan_partials(
    const int* __restrict__ count, int N, int* __restrict__ partial)
{
    __shared__ int ssum[256];
    int b = blockIdx.x, t = threadIdx.x;
    int s = 0;
#pragma unroll
    for (int j = 0; j < 4; j++) {
        int idx = b * SCAN_C + t * 4 + j;
        if (idx < N) s += count[idx];
    }
    ssum[t] = s;
    __syncthreads();
    for (int off = 128; off > 0; off >>= 1) {
        if (t < off) ssum[t] += ssum[t + off];
        __syncthreads();
    }
    if (t == 0) partial[b] = ssum[0];
}

__global__ void scan_block(int* __restrict__ partial, int nb)
{
    __shared__ int sp[64];
    int t = threadIdx.x;
    int v = (t < nb) ? partial[t] : 0;
    sp[t] = v;
    __syncthreads();
    for (int off = 1; off < 64; off <<= 1) {
        int x = (t >= off) ? sp[t - off] : 0;
        __syncthreads();
        sp[t] += x;
        __syncthreads();
    }
    if (t < nb) partial[t] = sp[t] - v;  // exclusive
}

__global__ void __launch_bounds__(256) scan_write(
    const int* __restrict__ count, const int* __restrict__ partial, int N,
    int* __restrict__ rowptr, int* __restrict__ nxt, float* __restrict__ degf)
{
    __shared__ int svals[256];
    int b = blockIdx.x, t = threadIdx.x;
    int v[4];
    int s = 0;
#pragma unroll
    for (int j = 0; j < 4; j++) {
        int idx = b * SCAN_C + t * 4 + j;
        v[j] = (idx < N) ? count[idx] : 0;
        s += v[j];
    }
    svals[t] = s;
    __syncthreads();
    int mine = s;
    for (int off = 1; off < 256; off <<= 1) {
        int x = (t >= off) ? svals[t - off] : 0;
        __syncthreads();
        svals[t] += x;
        __syncthreads();
    }
    int exc = svals[t] - mine + partial[b];
#pragma unroll
    for (int j = 0; j < 4; j++) {
        int idx = b * SCAN_C + t * 4 + j;
        if (idx < N) {
            rowptr[idx] = exc;
            nxt[idx] = exc;
            degf[idx] = (float)v[j];
            exc += v[j];
        }
    }
}

// ---------------- CSR fill ----------------
__global__ void __launch_bounds__(256) csr_fill(
    const void* __restrict__ ei, int E, int N, int* __restrict__ nxt,
    int* __restrict__ eid, int* __restrict__ srcid)
{
    int is64 = g_is64;
    for (int e = blockIdx.x * blockDim.x + threadIdx.x; e < E;
         e += gridDim.x * blockDim.x) {
        int s = load_idx(ei, e, is64);
        int d = load_idx(ei, (long long)E + e, is64);
        if ((unsigned)d >= (unsigned)N || (unsigned)s >= (unsigned)N) continue;
        int pos = atomicAdd(&nxt[d], 1);
        eid[pos] = e;
        srcid[pos] = s;
    }
}

// ---------------- edge moments: S = sum attr, M = sum attr attr^T ------------
__global__ void __launch_bounds__(256) edge_moments(
    const float* __restrict__ attr, int E, float* __restrict__ mom)
{
    __shared__ float sa[128 * ED];
    int tid = threadIdx.x;
    int k = tid & 15, l = tid >> 4;
    float m = 0.f, s = 0.f;
    for (int base = blockIdx.x * 128; base < E; base += gridDim.x * 128) {
        int ne = min(128, E - base);
        __syncthreads();
        for (int i = tid; i < ne * ED; i += 256)
            sa[i] = attr[(long long)base * ED + i];
        __syncthreads();
        for (int e = 0; e < ne; e++) {
            float ak = sa[e * ED + k];
            float al = sa[e * ED + l];
            m = fmaf(ak, al, m);
            if (l == 0) s += ak;
        }
    }
    atomicAdd(&mom[16 + l * 16 + k], m);
    if (l == 0) atomicAdd(&mom[k], s);
}

// ---------------- finalize edge BN from moments ------------------------------
__global__ void __launch_bounds__(128) finalize_ee_bn(
    const float* __restrict__ mom, const float* __restrict__ w1,
    const float* __restrict__ b1, const float* __restrict__ gamma,
    const float* __restrict__ beta, float invE,
    float* __restrict__ scale, float* __restrict__ shift)
{
    __shared__ float S[16], M[256];
    int c = threadIdx.x;
    if (c < 16) S[c] = mom[c];
    M[c] = mom[16 + c];
    M[128 + c] = mom[144 + c];
    __syncthreads();

    float wc[16];
#pragma unroll
    for (int k = 0; k < 16; k++) wc[k] = w1[k * D + c];
    float sw = 0.f;
#pragma unroll
    for (int k = 0; k < 16; k++) sw = fmaf(S[k], wc[k], sw);
    float bc = b1[c];
    float mean = sw * invE + bc;
    float q = 0.f;
#pragma unroll
    for (int k = 0; k < 16; k++) {
        float t = 0.f;
#pragma unroll
        for (int l = 0; l < 16; l++) t = fmaf(M[k * 16 + l], wc[l], t);
        q = fmaf(wc[k], t, q);
    }
    float ex2 = q * invE + 2.f * bc * sw * invE + bc * bc;
    float var = ex2 - mean * mean;
    float inv = rsqrtf(var + 1e-5f);
    float sc = gamma[c] * inv;
    scale[c] = sc;
    shift[c] = beta[c] - mean * sc;
}

// ---------------- finalize BN: scale/shift from colstats ---------------------
__global__ void finalize_bn(const float* __restrict__ stats,
                            const float* __restrict__ gamma,
                            const float* __restrict__ beta,
                            float invn, float* __restrict__ scale,
                            float* __restrict__ shift)
{
    int c = threadIdx.x;
    float mean = stats[c] * invn;
    float var = stats[128 + c] * invn - mean * mean;
    float inv = rsqrtf(var + 1e-5f);
    float sc = gamma[c] * inv;
    scale[c] = sc;
    shift[c] = beta[c] - mean * sc;
}

// ---------------- agg gather: agg[i] = sum_{e: dst=i} relu(BN(attr_e@W1)) ----
// warp per node, lane owns 4 columns; no atomics, full overwrite of agg.
__global__ void __launch_bounds__(256) agg_gather(
    const float* __restrict__ attr, const int* __restrict__ rowptr,
    const float* __restrict__ degf, const int* __restrict__ eid,
    const float* __restrict__ w1, const float* __restrict__ b1,
    const float* __restrict__ scale, const float* __restrict__ shift,
    int N, float* __restrict__ agg)
{
    int lane = threadIdx.x & 31;
    int warp = threadIdx.x >> 5;
    int node = blockIdx.x * 8 + warp;
    if (node >= N) return;
    int c4 = lane * 4;

    float4 w[ED];
#pragma unroll
    for (int k = 0; k < ED; k++) w[k] = *(const float4*)&w1[k * D + c4];
    float4 bb = *(const float4*)&b1[c4];
    float4 sc = *(const float4*)&scale[c4];
    float4 sh = *(const float4*)&shift[c4];
    sh.x = fmaf(bb.x, sc.x, sh.x);
    sh.y = fmaf(bb.y, sc.y, sh.y);
    sh.z = fmaf(bb.z, sc.z, sh.z);
    sh.w = fmaf(bb.w, sc.w, sh.w);

    int base = rowptr[node];
    int cnt = (int)degf[node];
    float4 acc = make_float4(0.f, 0.f, 0.f, 0.f);
    for (int j = 0; j < cnt; j++) {
        int e = eid[base + j];
        const float4* ap = (const float4*)(attr + (long long)e * ED);
        float4 a0 = __ldg(ap), a1 = __ldg(ap + 1), a2 = __ldg(ap + 2), a3 = __ldg(ap + 3);
        float av[16] = {a0.x, a0.y, a0.z, a0.w, a1.x, a1.y, a1.z, a1.w,
                        a2.x, a2.y, a2.z, a2.w, a3.x, a3.y, a3.z, a3.w};
        float4 t = make_float4(0.f, 0.f, 0.f, 0.f);
#pragma unroll
        for (int k = 0; k < ED; k++) {
            t.x = fmaf(av[k], w[k].x, t.x);
            t.y = fmaf(av[k], w[k].y, t.y);
            t.z = fmaf(av[k], w[k].z, t.z);
            t.w = fmaf(av[k], w[k].w, t.w);
        }
        acc.x += fmaxf(fmaf(t.x, sc.x, sh.x), 0.f);
        acc.y += fmaxf(fmaf(t.y, sc.y, sh.y), 0.f);
        acc.z += fmaxf(fmaf(t.z, sc.z, sh.z), 0.f);
        acc.w += fmaxf(fmaf(t.w, sc.w, sh.w), 0.f);
    }
    *(float4*)&agg[(long long)node * D + c4] = acc;
}

// ---------------- neigh gather: neigh[i] = sum_{e: dst=i} hnew[src_e] -------
__global__ void __launch_bounds__(256) neigh_gather(
    const float* __restrict__ hnew, const int* __restrict__ rowptr,
    const float* __restrict__ degf, const int* __restrict__ srcid,
    int N, float* __restrict__ neigh)
{
    int lane = threadIdx.x & 31;
    int warp = threadIdx.x >> 5;
    int node = blockIdx.x * 8 + warp;
    if (node >= N) return;
    int c4 = lane * 4;
    int base = rowptr[node];
    int cnt = (int)degf[node];
    float4 acc = make_float4(0.f, 0.f, 0.f, 0.f);
    for (int j = 0; j < cnt; j++) {
        int s = srcid[base + j];
        float4 v = __ldg((const float4*)&hnew[(long long)s * D + c4]);
        acc.x += v.x; acc.y += v.y; acc.z += v.z; acc.w += v.w;
    }
    *(float4*)&neigh[(long long)node * D + c4] = acc;
}

// ---------------- 128-wide K SIMT GEMM with fused pre/post + colstats -------
// MODE 0: out = A@W + hin + deg*bias
// MODE 1: out = (A + A2)@W + bias
// MODE 2: out = relu(A*scale+shift)@W + bias
#define GEMM_SMEM ((128 * 132 + 128 * 128) * 4)
template <int MODE, int STATS>
__global__ void __launch_bounds__(256) gemm128(
    const float* __restrict__ A, const float* __restrict__ A2,
    const float* __restrict__ W, const float* __restrict__ bias,
    const float* __restrict__ scale, const float* __restrict__ shift,
    const float* __restrict__ hin, const float* __restrict__ degv,
    float* __restrict__ out, float* __restrict__ stats, int N)
{
    extern __shared__ float sm[];
    float* As = sm;              // transposed, padded: As[k*132 + r]
    float* Ws = sm + 128 * 132;  // Ws[k*128 + c]
    int tid = threadIdx.x;
    int row0 = blockIdx.x * 128;

    for (int i = tid; i < 128 * 128; i += 256) Ws[i] = W[i];
    for (int i = tid; i < 128 * 128; i += 256) {
        int r = i >> 7, k = i & 127;
        int row = row0 + r;
        float v = 0.f;
        if (row < N) {
            v = A[(long long)row * D + k];
            if (MODE == 1) v += A2[(long long)row * D + k];
            if (MODE == 2) v = fmaxf(fmaf(v, scale[k], shift[k]), 0.f);
        }
        As[k * 132 + r] = v;
    }
    __syncthreads();

    int tx = tid & 15, ty = tid >> 4;
    float acc[8][8];
#pragma unroll
    for (int i = 0; i < 8; i++)
#pragma unroll
        for (int j = 0; j < 8; j++) acc[i][j] = 0.f;

    for (int k = 0; k < 128; k++) {
        float4 a0 = *(const float4*)&As[k * 132 + ty * 8];
        float4 a1 = *(const float4*)&As[k * 132 + ty * 8 + 4];
        float4 b0 = *(const float4*)&Ws[k * 128 + tx * 8];
        float4 b1 = *(const float4*)&Ws[k * 128 + tx * 8 + 4];
        float a[8] = {a0.x, a0.y, a0.z, a0.w, a1.x, a1.y, a1.z, a1.w};
        float b[8] = {b0.x, b0.y, b0.z, b0.w, b1.x, b1.y, b1.z, b1.w};
#pragma unroll
        for (int i = 0; i < 8; i++)
#pragma unroll
            for (int j = 0; j < 8; j++) acc[i][j] = fmaf(a[i], b[j], acc[i][j]);
    }

    float bs[8];
#pragma unroll
    for (int j = 0; j < 8; j++) bs[j] = bias[tx * 8 + j];

    float s1[8], s2[8];
#pragma unroll
    for (int j = 0; j < 8; j++) { s1[j] = 0.f; s2[j] = 0.f; }

#pragma unroll
    for (int i = 0; i < 8; i++) {
        int row = row0 + ty * 8 + i;
        if (row < N) {
            float o[8];
            if (MODE == 0) {
                float dg = degv[row];
                float4 h0 = *(const float4*)&hin[(long long)row * D + tx * 8];
                float4 h1 = *(const float4*)&hin[(long long)row * D + tx * 8 + 4];
                float hh[8] = {h0.x, h0.y, h0.z, h0.w, h1.x, h1.y, h1.z, h1.w};
#pragma unroll
                for (int j = 0; j < 8; j++) o[j] = acc[i][j] + hh[j] + dg * bs[j];
            } else {
#pragma unroll
                for (int j = 0; j < 8; j++) o[j] = acc[i][j] + bs[j];
            }
            if (STATS) {
#pragma unroll
                for (int j = 0; j < 8; j++) {
                    s1[j] += o[j];
                    s2[j] = fmaf(o[j], o[j], s2[j]);
                }
            }
            *(float4*)&out[(long long)row * D + tx * 8] = make_float4(o[0], o[1], o[2], o[3]);
            *(float4*)&out[(long long)row * D + tx * 8 + 4] = make_float4(o[4], o[5], o[6], o[7]);
        }
    }

    if (STATS) {
        __syncthreads();  // done reading As; reuse for staging
        float* p1 = sm;           // [16][128]
        float* p2 = sm + 2048;    // [16][128]
#pragma unroll
        for (int j = 0; j < 8; j++) {
            p1[ty * 128 + tx * 8 + j] = s1[j];
            p2[ty * 128 + tx * 8 + j] = s2[j];
        }
        __syncthreads();
        if (tid < 128) {
            float a = 0.f, b = 0.f;
#pragma unroll
            for (int r = 0; r < 16; r++) {
                a += p1[r * 128 + tid];
                b += p2[r * 128 + tid];
            }
            atomicAdd(&stats[tid], a);
            atomicAdd(&stats[128 + tid], b);
        }
    }
}

// ---------------- final eltwise: out = relu(bn(t2)) ----------------
__global__ void __launch_bounds__(256) bn_relu_out(
    const float* __restrict__ t2, const float* __restrict__ scale,
    const float* __restrict__ shift, float* __restrict__ out, int N)
{
    int total4 = N * 32;
    for (int idx = blockIdx.x * blockDim.x + threadIdx.x; idx < total4;
         idx += gridDim.x * blockDim.x) {
        int c4 = (idx & 31) * 4;
        float4 v = *(const float4*)&t2[(long long)idx * 4];
        float4 sc = *(const float4*)&scale[c4];
        float4 sh = *(const float4*)&shift[c4];
        float4 o;
        o.x = fmaxf(fmaf(v.x, sc.x, sh.x), 0.f);
        o.y = fmaxf(fmaf(v.y, sc.y, sh.y), 0.f);
        o.z = fmaxf(fmaf(v.z, sc.z, sh.z), 0.f);
        o.w = fmaxf(fmaf(v.w, sc.w, sh.w), 0.f);
        *(float4*)&out[(long long)idx * 4] = o;
    }
}

// ---------------- launch ----------------
extern "C" void kernel_launch(void* const* d_in, const int* in_sizes, int n_in,
                              void* d_out, int out_size)
{
    const float* h        = (const float*)d_in[0];
    const void*  ei       = d_in[1];
    const float* attr     = (const float*)d_in[2];
    const float* ee_w1    = (const float*)d_in[3];
    const float* ee_b1    = (const float*)d_in[4];
    const float* ee_g1    = (const float*)d_in[5];
    const float* ee_bb1   = (const float*)d_in[6];
    const float* ee_w2    = (const float*)d_in[7];
    const float* ee_b2    = (const float*)d_in[8];
    const float* mlp_w1   = (const float*)d_in[9];
    const float* mlp_b1   = (const float*)d_in[10];
    const float* mlp_g1   = (const float*)d_in[11];
    const float* mlp_bb1  = (const float*)d_in[12];
    const float* mlp_w2   = (const float*)d_in[13];
    const float* mlp_b2   = (const float*)d_in[14];
    const float* mlp_g2   = (const float*)d_in[15];
    const float* mlp_bb2  = (const float*)d_in[16];

    int N = in_sizes[0] / D;
    int E = in_sizes[1] / 2;
    float* out = (float*)d_out;

    float *p_agg, *p_deg, *p_hnew, *p_neigh, *p_t1, *p_t2, *p_stats, *p_mom, *p_scale, *p_shift;
    int *p_count, *p_rowptr, *p_next, *p_eid, *p_srcid, *p_partial;
    cudaGetSymbolAddress((void**)&p_agg, g_agg);
    cudaGetSymbolAddress((void**)&p_deg, g_deg);
    cudaGetSymbolAddress((void**)&p_hnew, g_hnew);
    cudaGetSymbolAddress((void**)&p_neigh, g_neigh);
    cudaGetSymbolAddress((void**)&p_t1, g_t1);
    cudaGetSymbolAddress((void**)&p_t2, g_t2);
    cudaGetSymbolAddress((void**)&p_stats, g_stats);
    cudaGetSymbolAddress((void**)&p_mom, g_mom);
    cudaGetSymbolAddress((void**)&p_scale, g_scale);
    cudaGetSymbolAddress((void**)&p_shift, g_shift);
    cudaGetSymbolAddress((void**)&p_count, g_count);
    cudaGetSymbolAddress((void**)&p_rowptr, g_rowptr);
    cudaGetSymbolAddress((void**)&p_next, g_next);
    cudaGetSymbolAddress((void**)&p_eid, g_eid);
    cudaGetSymbolAddress((void**)&p_srcid, g_srcid);
    cudaGetSymbolAddress((void**)&p_partial, g_partial);

    cudaFuncSetAttribute(gemm128<0,0>, cudaFuncAttributeMaxDynamicSharedMemorySize, GEMM_SMEM);
    cudaFuncSetAttribute(gemm128<1,1>, cudaFuncAttributeMaxDynamicSharedMemorySize, GEMM_SMEM);
    cudaFuncSetAttribute(gemm128<2,1>, cudaFuncAttributeMaxDynamicSharedMemorySize, GEMM_SMEM);

    int tiles = (N + 127) / 128;
    int nscan = (N + SCAN_C - 1) / SCAN_C;
    int ngather = (N + 7) / 8;

    detect_idx<<<1, 32>>>((const unsigned long long*)ei, E);
    zero_small<<<256, 256>>>(p_count, p_stats, p_mom, N);

    // CSR build (by dst)
    hist_dst<<<1184, 256>>>(ei, E, N, p_count);
    scan_partials<<<nscan, 256>>>(p_count, N, p_partial);
    scan_block<<<1, 64>>>(p_partial, nscan);
    scan_write<<<nscan, 256>>>(p_count, p_partial, N, p_rowptr, p_next, p_deg);
    csr_fill<<<1184, 256>>>(ei, E, N, p_next, p_eid, p_srcid);

    // edge encoder BN stats via closed-form moments
    edge_moments<<<1184, 256>>>(attr, E, p_mom);
    finalize_ee_bn<<<1, 128>>>(p_mom, ee_w1, ee_b1, ee_g1, ee_bb1,
                               1.0f / (float)E, p_scale, p_shift);

    // agg = segment_sum(relu(BN(attr@W1)), dst)  — gather, no atomics
    agg_gather<<<ngather, 256>>>(attr, p_rowptr, p_deg, p_eid,
                                 ee_w1, ee_b1, p_scale, p_shift, N, p_agg);

    // h_new = h + agg@ee_w2 + deg*ee_b2
    gemm128<0,0><<<tiles, 256, GEMM_SMEM>>>(p_agg, nullptr, ee_w2, ee_b2,
                                            nullptr, nullptr, h, p_deg, p_hnew,
                                            nullptr, N);

    // neigh = segment_sum(h_new[src], dst) — gather, no atomics
    neigh_gather<<<ngather, 256>>>(p_hnew, p_rowptr, p_deg, p_srcid, N, p_neigh);

    // t1 = (h_new + neigh) @ mlp_w1 + b1   (+ fused colstats)
    gemm128<1,1><<<tiles, 256, GEMM_SMEM>>>(p_hnew, p_neigh, mlp_w1, mlp_b1,
                                            nullptr, nullptr, nullptr, nullptr,
                                            p_t1, p_stats + 256, N);
    finalize_bn<<<1, 128>>>(p_stats + 256, mlp_g1, mlp_bb1, 1.0f / (float)N,
                            p_scale + 128, p_shift + 128);

    // t2 = relu(bn(t1)) @ mlp_w2 + b2   (+ fused colstats)
    gemm128<2,1><<<tiles, 256, GEMM_SMEM>>>(p_t1, nullptr, mlp_w2, mlp_b2,
                                            p_scale + 128, p_shift + 128,
                                            nullptr, nullptr, p_t2,
                                            p_stats + 512, N);
    finalize_bn<<<1, 128>>>(p_stats + 512, mlp_g2, mlp_bb2, 1.0f / (float)N,
                            p_scale + 256, p_shift + 256);

    // out = relu(bn(t2))
    int g = min((N * 32 + 255) / 256, 4096);
    bn_relu_out<<<g, 256>>>(p_t2, p_scale + 256, p_shift + 256, out, N);
}

// round 8
// speedup vs baseline: 1.1809x; 1.0140x over previous
#include <cuda_runtime.h>
#include <cuda_bf16.h>

// Problem-fixed shapes
#define MAXN 50000
#define MAXE 600000
#define D 128
#define ED 16

typedef unsigned long long ull;

// packed fp32x2 helpers (sm_103a)
#define FMA2(d, a, b, c) \
    asm("fma.rn.f32x2 %0, %1, %2, %3;" : "=l"(d) : "l"(a), "l"(b), "l"(c))
#define PACK2(d, lo, hi) \
    asm("mov.b64 %0, {%1, %2};" : "=l"(d) \
        : "r"(__float_as_uint(lo)), "r"(__float_as_uint(hi)))

__device__ __forceinline__ float2 upk2(ull v) {
    unsigned lo, hi;
    asm("mov.b64 {%0, %1}, %2;" : "=r"(lo), "=r"(hi) : "l"(v));
    return make_float2(__uint_as_float(lo), __uint_as_float(hi));
}

// ---------------- device scratch ----------------
__device__ float g_agg[MAXN * D];
__device__ float g_deg[MAXN];
__device__ float g_hnew[MAXN * D];
__device__ float g_neigh[MAXN * D];
__device__ float g_t1[MAXN * D];
__device__ float g_t2[MAXN * D];
__device__ float g_stats[3 * 256];
__device__ float g_mom[16 + 256];
__device__ float g_scale[3 * 128];
__device__ float g_shift[3 * 128];
__device__ int   g_is64;
// CSR by destination
__device__ int   g_count[MAXN];
__device__ int   g_rowptr[MAXN];
__device__ int   g_next[MAXN];
__device__ int   g_eid[MAXE];
__device__ int   g_srcid[MAXE];
__device__ int   g_partial[64];

__device__ __forceinline__ int load_idx(const void* ei, long long pos, int is64)
{
    if (is64) return (int)((const long long*)ei)[pos];
    return ((const int*)ei)[pos];
}

// ---------------- zero small accumulators + detect idx dtype ----------------
__global__ void __launch_bounds__(256) zero_small(
    const unsigned long long* __restrict__ ei, int E,
    int* __restrict__ count, float* __restrict__ stats,
    float* __restrict__ mom, int N)
{
    int gtid = blockIdx.x * blockDim.x + threadIdx.x;
    if (gtid == 0) {
        int n = E < 1024 ? E : 1024;
        int is64 = 1;
        for (int i = 0; i < n; i++)
            if (ei[i] >> 32) { is64 = 0; break; }
        g_is64 = is64;
    }
    for (int i = gtid; i < N; i += gridDim.x * blockDim.x) count[i] = 0;
    if (gtid < 768) stats[gtid] = 0.f;
    if (gtid < 272) mom[gtid] = 0.f;
}

// ---------------- histogram of dst ----------------
__global__ void __launch_bounds__(256) hist_dst(
    const void* __restrict__ ei, int E, int N, int* __restrict__ count)
{
    int is64 = g_is64;
    for (int e = blockIdx.x * blockDim.x + threadIdx.x; e < E;
         e += gridDim.x * blockDim.x) {
        int d = load_idx(ei, (long long)E + e, is64);
        if ((unsigned)d < (unsigned)N) atomicAdd(&count[d], 1);
    }
}

// ---------------- 3-kernel exclusive scan over count[N] ----------------
#define SCAN_C 1024
__global__ void __launch_bounds__(256) scan_partials(
    const int* __restrict__ count, int N, int* __restrict__ partial)
{
    __shared__ int ssum[256];
    int b = blockIdx.x, t = threadIdx.x;
    int s = 0;
#pragma unroll
    for (int j = 0; j < 4; j++) {
        int idx = b * SCAN_C + t * 4 + j;
        if (idx < N) s += count[idx];
    }
    ssum[t] = s;
    __syncthreads();
    for (int off = 128; off > 0; off >>= 1) {
        if (t < off) ssum[t] += ssum[t + off];
        __syncthreads();
    }
    if (t == 0) partial[b] = ssum[0];
}

__global__ void scan_block(int* __restrict__ partial, int nb)
{
    __shared__ int sp[64];
    int t = threadIdx.x;
    int v = (t < nb) ? partial[t] : 0;
    sp[t] = v;
    __syncthreads();
    for (int off = 1; off < 64; off <<= 1) {
        int x = (t >= off) ? sp[t - off] : 0;
        __syncthreads();
        sp[t] += x;
        __syncthreads();
    }
    if (t < nb) partial[t] = sp[t] - v;
}

__global__ void __launch_bounds__(256) scan_write(
    const int* __restrict__ count, const int* __restrict__ partial, int N,
    int* __restrict__ rowptr, int* __restrict__ nxt, float* __restrict__ degf)
{
    __shared__ int svals[256];
    int b = blockIdx.x, t = threadIdx.x;
    int v[4];
    int s = 0;
#pragma unroll
    for (int j = 0; j < 4; j++) {
        int idx = b * SCAN_C + t * 4 + j;
        v[j] = (idx < N) ? count[idx] : 0;
        s += v[j];
    }
    svals[t] = s;
    __syncthreads();
    int mine = s;
    for (int off = 1; off < 256; off <<= 1) {
        int x = (t >= off) ? svals[t - off] : 0;
        __syncthreads();
        svals[t] += x;
        __syncthreads();
    }
    int exc = svals[t] - mine + partial[b];
#pragma unroll
    for (int j = 0; j < 4; j++) {
        int idx = b * SCAN_C + t * 4 + j;
        if (idx < N) {
            rowptr[idx] = exc;
            nxt[idx] = exc;
            degf[idx] = (float)v[j];
            exc += v[j];
        }
    }
}

// ---------------- CSR fill ----------------
__global__ void __launch_bounds__(256) csr_fill(
    const void* __restrict__ ei, int E, int N, int* __restrict__ nxt,
    int* __restrict__ eid, int* __restrict__ srcid)
{
    int is64 = g_is64;
    for (int e = blockIdx.x * blockDim.x + threadIdx.x; e < E;
         e += gridDim.x * blockDim.x) {
        int s = load_idx(ei, e, is64);
        int d = load_idx(ei, (long long)E + e, is64);
        if ((unsigned)d >= (unsigned)N || (unsigned)s >= (unsigned)N) continue;
        int pos = atomicAdd(&nxt[d], 1);
        eid[pos] = e;
        srcid[pos] = s;
    }
}

// ---------------- edge moments ----------------
__global__ void __launch_bounds__(256) edge_moments(
    const float* __restrict__ attr, int E, float* __restrict__ mom)
{
    __shared__ float sa[128 * ED];
    int tid = threadIdx.x;
    int k = tid & 15, l = tid >> 4;
    float m = 0.f, s = 0.f;
    for (int base = blockIdx.x * 128; base < E; base += gridDim.x * 128) {
        int ne = min(128, E - base);
        __syncthreads();
        for (int i = tid; i < ne * ED; i += 256)
            sa[i] = attr[(long long)base * ED + i];
        __syncthreads();
        for (int e = 0; e < ne; e++) {
            float ak = sa[e * ED + k];
            float al = sa[e * ED + l];
            m = fmaf(ak, al, m);
            if (l == 0) s += ak;
        }
    }
    atomicAdd(&mom[16 + l * 16 + k], m);
    if (l == 0) atomicAdd(&mom[k], s);
}

// ---------------- finalize edge BN from moments ----------------
__global__ void __launch_bounds__(128) finalize_ee_bn(
    const float* __restrict__ mom, const float* __restrict__ w1,
    const float* __restrict__ b1, const float* __restrict__ gamma,
    const float* __restrict__ beta, float invE,
    float* __restrict__ scale, float* __restrict__ shift)
{
    __shared__ float S[16], M[256];
    int c = threadIdx.x;
    if (c < 16) S[c] = mom[c];
    M[c] = mom[16 + c];
    M[128 + c] = mom[144 + c];
    __syncthreads();

    float wc[16];
#pragma unroll
    for (int k = 0; k < 16; k++) wc[k] = w1[k * D + c];
    float sw = 0.f;
#pragma unroll
    for (int k = 0; k < 16; k++) sw = fmaf(S[k], wc[k], sw);
    float bc = b1[c];
    float mean = sw * invE + bc;
    float q = 0.f;
#pragma unroll
    for (int k = 0; k < 16; k++) {
        float t = 0.f;
#pragma unroll
        for (int l = 0; l < 16; l++) t = fmaf(M[k * 16 + l], wc[l], t);
        q = fmaf(wc[k], t, q);
    }
    float ex2 = q * invE + 2.f * bc * sw * invE + bc * bc;
    float var = ex2 - mean * mean;
    float inv = rsqrtf(var + 1e-5f);
    float sc = gamma[c] * inv;
    scale[c] = sc;
    shift[c] = beta[c] - mean * sc;
}

// ---------------- finalize BN from colstats ----------------
__global__ void finalize_bn(const float* __restrict__ stats,
                            const float* __restrict__ gamma,
                            const float* __restrict__ beta,
                            float invn, float* __restrict__ scale,
                            float* __restrict__ shift)
{
    int c = threadIdx.x;
    float mean = stats[c] * invn;
    float var = stats[128 + c] * invn - mean * mean;
    float inv = rsqrtf(var + 1e-5f);
    float sc = gamma[c] * inv;
    scale[c] = sc;
    shift[c] = beta[c] - mean * sc;
}

// ---------------- agg gather with f32x2 dot products ----------------
__global__ void __launch_bounds__(256) agg_gather(
    const float* __restrict__ attr, const int* __restrict__ rowptr,
    const float* __restrict__ degf, const int* __restrict__ eid,
    const float* __restrict__ w1, const float* __restrict__ b1,
    const float* __restrict__ scale, const float* __restrict__ shift,
    int N, float* __restrict__ agg)
{
    int lane = threadIdx.x & 31;
    int warp = threadIdx.x >> 5;
    int node = blockIdx.x * 8 + warp;
    if (node >= N) return;
    int c4 = lane * 4;

    // packed weight pairs: wp0[k] = (w[k][c4], w[k][c4+1]), wp1[k] = (c4+2, c4+3)
    ull wp0[ED], wp1[ED];
#pragma unroll
    for (int k = 0; k < ED; k++) {
        const longlong2 wv = *(const longlong2*)&w1[k * D + c4];
        wp0[k] = (ull)wv.x;
        wp1[k] = (ull)wv.y;
    }
    float4 bb = *(const float4*)&b1[c4];
    float4 sc = *(const float4*)&scale[c4];
    float4 sh = *(const float4*)&shift[c4];
    sh.x = fmaf(bb.x, sc.x, sh.x);
    sh.y = fmaf(bb.y, sc.y, sh.y);
    sh.z = fmaf(bb.z, sc.z, sh.z);
    sh.w = fmaf(bb.w, sc.w, sh.w);

    int base = rowptr[node];
    int cnt = (int)degf[node];
    float4 acc = make_float4(0.f, 0.f, 0.f, 0.f);
    for (int j = 0; j < cnt; j++) {
        int e = eid[base + j];
        const float4* ap = (const float4*)(attr + (long long)e * ED);
        float4 a0 = __ldg(ap), a1 = __ldg(ap + 1), a2 = __ldg(ap + 2), a3 = __ldg(ap + 3);
        float av[16] = {a0.x, a0.y, a0.z, a0.w, a1.x, a1.y, a1.z, a1.w,
                        a2.x, a2.y, a2.z, a2.w, a3.x, a3.y, a3.z, a3.w};
        ull t0 = 0ull, t1 = 0ull;  // (0.0f, 0.0f) pairs
#pragma unroll
        for (int k = 0; k < ED; k++) {
            ull ak;
            PACK2(ak, av[k], av[k]);
            FMA2(t0, ak, wp0[k], t0);
            FMA2(t1, ak, wp1[k], t1);
        }
        float2 f0 = upk2(t0), f1 = upk2(t1);
        acc.x += fmaxf(fmaf(f0.x, sc.x, sh.x), 0.f);
        acc.y += fmaxf(fmaf(f0.y, sc.y, sh.y), 0.f);
        acc.z += fmaxf(fmaf(f1.x, sc.z, sh.z), 0.f);
        acc.w += fmaxf(fmaf(f1.y, sc.w, sh.w), 0.f);
    }
    *(float4*)&agg[(long long)node * D + c4] = acc;
}

// ---------------- neigh gather ----------------
__global__ void __launch_bounds__(256) neigh_gather(
    const float* __restrict__ hnew, const int* __restrict__ rowptr,
    const float* __restrict__ degf, const int* __restrict__ srcid,
    int N, float* __restrict__ neigh)
{
    int lane = threadIdx.x & 31;
    int warp = threadIdx.x >> 5;
    int node = blockIdx.x * 8 + warp;
    if (node >= N) return;
    int c4 = lane * 4;
    int base = rowptr[node];
    int cnt = (int)degf[node];
    float4 acc = make_float4(0.f, 0.f, 0.f, 0.f);
    for (int j = 0; j < cnt; j++) {
        int s = srcid[base + j];
        float4 v = __ldg((const float4*)&hnew[(long long)s * D + c4]);
        acc.x += v.x; acc.y += v.y; acc.z += v.z; acc.w += v.w;
    }
    *(float4*)&neigh[(long long)node * D + c4] = acc;
}

// ---------------- 128-wide K SIMT GEMM (f32x2 inner) + fused pre/post -------
// MODE 0: out = A@W + hin + deg*bias
// MODE 1: out = (A + A2)@W + bias
// MODE 2: out = relu(A*scale+shift)@W + bias
#define GEMM_SMEM ((128 * 132 + 128 * 128) * 4)
template <int MODE, int STATS>
__global__ void __launch_bounds__(256) gemm128(
    const float* __restrict__ A, const float* __restrict__ A2,
    const float* __restrict__ W, const float* __restrict__ bias,
    const float* __restrict__ scale, const float* __restrict__ shift,
    const float* __restrict__ hin, const float* __restrict__ degv,
    float* __restrict__ out, float* __restrict__ stats, int N)
{
    extern __shared__ float sm[];
    float* As = sm;              // transposed, padded: As[k*132 + r]
    float* Ws = sm + 128 * 132;  // Ws[k*128 + c]
    int tid = threadIdx.x;
    int row0 = blockIdx.x * 128;

    for (int i = tid; i < 128 * 128; i += 256) Ws[i] = W[i];
    for (int i = tid; i < 128 * 128; i += 256) {
        int r = i >> 7, k = i & 127;
        int row = row0 + r;
        float v = 0.f;
        if (row < N) {
            v = A[(long long)row * D + k];
            if (MODE == 1) v += A2[(long long)row * D + k];
            if (MODE == 2) v = fmaxf(fmaf(v, scale[k], shift[k]), 0.f);
        }
        As[k * 132 + r] = v;
    }
    __syncthreads();

    int tx = tid & 15, ty = tid >> 4;
    // 8 rows x 4 packed col-pairs (same register budget as 8x8 floats)
    ull accp[8][4];
#pragma unroll
    for (int i = 0; i < 8; i++)
#pragma unroll
        for (int j = 0; j < 4; j++) accp[i][j] = 0ull;

    for (int k = 0; k < 128; k++) {
        float4 a0 = *(const float4*)&As[k * 132 + ty * 8];
        float4 a1 = *(const float4*)&As[k * 132 + ty * 8 + 4];
        longlong2 b01 = *(const longlong2*)&Ws[k * 128 + tx * 8];
        longlong2 b23 = *(const longlong2*)&Ws[k * 128 + tx * 8 + 4];
        ull bp[4] = {(ull)b01.x, (ull)b01.y, (ull)b23.x, (ull)b23.y};
        float a[8] = {a0.x, a0.y, a0.z, a0.w, a1.x, a1.y, a1.z, a1.w};
#pragma unroll
        for (int i = 0; i < 8; i++) {
            ull ai;
            PACK2(ai, a[i], a[i]);
#pragma unroll
            for (int j = 0; j < 4; j++)
                FMA2(accp[i][j], ai, bp[j], accp[i][j]);
        }
    }

    float bs[8];
#pragma unroll
    for (int j = 0; j < 8; j++) bs[j] = bias[tx * 8 + j];

    float s1[8], s2[8];
#pragma unroll
    for (int j = 0; j < 8; j++) { s1[j] = 0.f; s2[j] = 0.f; }

#pragma unroll
    for (int i = 0; i < 8; i++) {
        int row = row0 + ty * 8 + i;
        if (row < N) {
            float acc[8];
#pragma unroll
            for (int j = 0; j < 4; j++) {
                float2 f = upk2(accp[i][j]);
                acc[j * 2] = f.x;
                acc[j * 2 + 1] = f.y;
            }
            float o[8];
            if (MODE == 0) {
                float dg = degv[row];
                float4 h0 = *(const float4*)&hin[(long long)row * D + tx * 8];
                float4 h1 = *(const float4*)&hin[(long long)row * D + tx * 8 + 4];
                float hh[8] = {h0.x, h0.y, h0.z, h0.w, h1.x, h1.y, h1.z, h1.w};
#pragma unroll
                for (int j = 0; j < 8; j++) o[j] = acc[j] + hh[j] + dg * bs[j];
            } else {
#pragma unroll
                for (int j = 0; j < 8; j++) o[j] = acc[j] + bs[j];
            }
            if (STATS) {
#pragma unroll
                for (int j = 0; j < 8; j++) {
                    s1[j] += o[j];
                    s2[j] = fmaf(o[j], o[j], s2[j]);
                }
            }
            *(float4*)&out[(long long)row * D + tx * 8] = make_float4(o[0], o[1], o[2], o[3]);
            *(float4*)&out[(long long)row * D + tx * 8 + 4] = make_float4(o[4], o[5], o[6], o[7]);
        }
    }

    if (STATS) {
        __syncthreads();
        float* p1 = sm;
        float* p2 = sm + 2048;
#pragma unroll
        for (int j = 0; j < 8; j++) {
            p1[ty * 128 + tx * 8 + j] = s1[j];
            p2[ty * 128 + tx * 8 + j] = s2[j];
        }
        __syncthreads();
        if (tid < 128) {
            float a = 0.f, b = 0.f;
#pragma unroll
            for (int r = 0; r < 16; r++) {
                a += p1[r * 128 + tid];
                b += p2[r * 128 + tid];
            }
            atomicAdd(&stats[tid], a);
            atomicAdd(&stats[128 + tid], b);
        }
    }
}

// ---------------- final eltwise: out = relu(bn(t2)) ----------------
__global__ void __launch_bounds__(256) bn_relu_out(
    const float* __restrict__ t2, const float* __restrict__ scale,
    const float* __restrict__ shift, float* __restrict__ out, int N)
{
    int total4 = N * 32;
    for (int idx = blockIdx.x * blockDim.x + threadIdx.x; idx < total4;
         idx += gridDim.x * blockDim.x) {
        int c4 = (idx & 31) * 4;
        float4 v = *(const float4*)&t2[(long long)idx * 4];
        float4 sc = *(const float4*)&scale[c4];
        float4 sh = *(const float4*)&shift[c4];
        float4 o;
        o.x = fmaxf(fmaf(v.x, sc.x, sh.x), 0.f);
        o.y = fmaxf(fmaf(v.y, sc.y, sh.y), 0.f);
        o.z = fmaxf(fmaf(v.z, sc.z, sh.z), 0.f);
        o.w = fmaxf(fmaf(v.w, sc.w, sh.w), 0.f);
        *(float4*)&out[(long long)idx * 4] = o;
    }
}

// ---------------- launch ----------------
extern "C" void kernel_launch(void* const* d_in, const int* in_sizes, int n_in,
                              void* d_out, int out_size)
{
    const float* h        = (const float*)d_in[0];
    const void*  ei       = d_in[1];
    const float* attr     = (const float*)d_in[2];
    const float* ee_w1    = (const float*)d_in[3];
    const float* ee_b1    = (const float*)d_in[4];
    const float* ee_g1    = (const float*)d_in[5];
    const float* ee_bb1   = (const float*)d_in[6];
    const float* ee_w2    = (const float*)d_in[7];
    const float* ee_b2    = (const float*)d_in[8];
    const float* mlp_w1   = (const float*)d_in[9];
    const float* mlp_b1   = (const float*)d_in[10];
    const float* mlp_g1   = (const float*)d_in[11];
    const float* mlp_bb1  = (const float*)d_in[12];
    const float* mlp_w2   = (const float*)d_in[13];
    const float* mlp_b2   = (const float*)d_in[14];
    const float* mlp_g2   = (const float*)d_in[15];
    const float* mlp_bb2  = (const float*)d_in[16];

    int N = in_sizes[0] / D;
    int E = in_sizes[1] / 2;
    float* out = (float*)d_out;

    float *p_agg, *p_deg, *p_hnew, *p_neigh, *p_t1, *p_t2, *p_stats, *p_mom, *p_scale, *p_shift;
    int *p_count, *p_rowptr, *p_next, *p_eid, *p_srcid, *p_partial;
    cudaGetSymbolAddress((void**)&p_agg, g_agg);
    cudaGetSymbolAddress((void**)&p_deg, g_deg);
    cudaGetSymbolAddress((void**)&p_hnew, g_hnew);
    cudaGetSymbolAddress((void**)&p_neigh, g_neigh);
    cudaGetSymbolAddress((void**)&p_t1, g_t1);
    cudaGetSymbolAddress((void**)&p_t2, g_t2);
    cudaGetSymbolAddress((void**)&p_stats, g_stats);
    cudaGetSymbolAddress((void**)&p_mom, g_mom);
    cudaGetSymbolAddress((void**)&p_scale, g_scale);
    cudaGetSymbolAddress((void**)&p_shift, g_shift);
    cudaGetSymbolAddress((void**)&p_count, g_count);
    cudaGetSymbolAddress((void**)&p_rowptr, g_rowptr);
    cudaGetSymbolAddress((void**)&p_next, g_next);
    cudaGetSymbolAddress((void**)&p_eid, g_eid);
    cudaGetSymbolAddress((void**)&p_srcid, g_srcid);
    cudaGetSymbolAddress((void**)&p_partial, g_partial);

    cudaFuncSetAttribute(gemm128<0,0>, cudaFuncAttributeMaxDynamicSharedMemorySize, GEMM_SMEM);
    cudaFuncSetAttribute(gemm128<1,1>, cudaFuncAttributeMaxDynamicSharedMemorySize, GEMM_SMEM);
    cudaFuncSetAttribute(gemm128<2,1>, cudaFuncAttributeMaxDynamicSharedMemorySize, GEMM_SMEM);

    int tiles = (N + 127) / 128;
    int nscan = (N + SCAN_C - 1) / SCAN_C;
    int ngather = (N + 7) / 8;

    zero_small<<<256, 256>>>((const unsigned long long*)ei, E, p_count, p_stats, p_mom, N);

    // CSR build (by dst)
    hist_dst<<<1184, 256>>>(ei, E, N, p_count);
    scan_partials<<<nscan, 256>>>(p_count, N, p_partial);
    scan_block<<<1, 64>>>(p_partial, nscan);
    scan_write<<<nscan, 256>>>(p_count, p_partial, N, p_rowptr, p_next, p_deg);
    csr_fill<<<1184, 256>>>(ei, E, N, p_next, p_eid, p_srcid);

    // edge encoder BN stats via closed-form moments
    edge_moments<<<1184, 256>>>(attr, E, p_mom);
    finalize_ee_bn<<<1, 128>>>(p_mom, ee_w1, ee_b1, ee_g1, ee_bb1,
                               1.0f / (float)E, p_scale, p_shift);

    // agg = segment_sum(relu(BN(attr@W1)), dst)
    agg_gather<<<ngather, 256>>>(attr, p_rowptr, p_deg, p_eid,
                                 ee_w1, ee_b1, p_scale, p_shift, N, p_agg);

    // h_new = h + agg@ee_w2 + deg*ee_b2
    gemm128<0,0><<<tiles, 256, GEMM_SMEM>>>(p_agg, nullptr, ee_w2, ee_b2,
                                            nullptr, nullptr, h, p_deg, p_hnew,
                                            nullptr, N);

    // neigh = segment_sum(h_new[src], dst)
    neigh_gather<<<ngather, 256>>>(p_hnew, p_rowptr, p_deg, p_srcid, N, p_neigh);

    // t1 = (h_new + neigh) @ mlp_w1 + b1   (+ fused colstats)
    gemm128<1,1><<<tiles, 256, GEMM_SMEM>>>(p_hnew, p_neigh, mlp_w1, mlp_b1,
                                            nullptr, nullptr, nullptr, nullptr,
                                            p_t1, p_stats + 256, N);
    finalize_bn<<<1, 128>>>(p_stats + 256, mlp_g1, mlp_bb1, 1.0f / (float)N,
                            p_scale + 128, p_shift + 128);

    // t2 = relu(bn(t1)) @ mlp_w2 + b2   (+ fused colstats)
    gemm128<2,1><<<tiles, 256, GEMM_SMEM>>>(p_t1, nullptr, mlp_w2, mlp_b2,
                                            p_scale + 128, p_shift + 128,
                                            nullptr, nullptr, p_t2,
                                            p_stats + 512, N);
    finalize_bn<<<1, 128>>>(p_stats + 512, mlp_g2, mlp_bb2, 1.0f / (float)N,
                            p_scale + 256, p_shift + 256);

    // out = relu(bn(t2))
    int g = min((N * 32 + 255) / 256, 4096);
    bn_relu_out<<<g, 256>>>(p_t2, p_scale + 256, p_shift + 256, out, N);
}